// round 1
// baseline (speedup 1.0000x reference)
#include <cuda_runtime.h>
#include <math.h>

// Problem dims
#define BDIM 1024
#define UDIM 2048
#define KDIM 4096   // 2*U
#define NDIM 8192   // 4*U

// Scratch for pre-activation gates (32 MB) — static __device__ per harness rules
__device__ float g_ifgo[(size_t)BDIM * NDIM];

// ---------------- GEMM: ifgo = concat(x,h) @ w ----------------
// Tile: BM=128, BN=128, BK=16; 256 threads; 8x8 microtile per thread.
#define BM 128
#define BN 128
#define BK 16
#define TM 8
#define TN 8

__global__ __launch_bounds__(256, 2)
void lstm_gemm_kernel(const float* __restrict__ x,
                      const float* __restrict__ h,
                      const float* __restrict__ w) {
    __shared__ float As[BK][BM + 2];  // +2 pad -> conflict-free transposed STS
    __shared__ float Bs[BK][BN];

    const int tid = threadIdx.x;
    const int block_m = blockIdx.y * BM;
    const int block_n = blockIdx.x * BN;

    const int tx = tid & 15;   // 0..15 -> n
    const int ty = tid >> 4;   // 0..15 -> m

    // A-tile load mapping: 128 rows x 16 cols, float4 along K
    const int a_r = tid >> 2;         // 0..63 (+64 second pass)
    const int a_c = (tid & 3) * 4;    // 0,4,8,12

    // B-tile load mapping: 16 rows(k) x 128 cols(n), float4 along N
    const int b_k = tid >> 5;         // 0..7 (+8 second pass)
    const int b_n = (tid & 31) * 4;

    float acc[TM][TN];
    #pragma unroll
    for (int i = 0; i < TM; i++)
        #pragma unroll
        for (int j = 0; j < TN; j++) acc[i][j] = 0.f;

    for (int k0 = 0; k0 < KDIM; k0 += BK) {
        // concat(x,h): K tile lies entirely in one half (2048 % 16 == 0)
        const float* abase = (k0 < UDIM) ? (x + k0) : (h + (k0 - UDIM));

        #pragma unroll
        for (int rr = 0; rr < 2; rr++) {
            const int r = a_r + rr * 64;
            const float4 v = *(const float4*)(abase + (size_t)(block_m + r) * UDIM + a_c);
            As[a_c + 0][r] = v.x;
            As[a_c + 1][r] = v.y;
            As[a_c + 2][r] = v.z;
            As[a_c + 3][r] = v.w;
        }
        #pragma unroll
        for (int rr = 0; rr < 2; rr++) {
            const int kk = b_k + rr * 8;
            const float4 v = *(const float4*)(w + (size_t)(k0 + kk) * NDIM + block_n + b_n);
            *(float4*)&Bs[kk][b_n] = v;
        }
        __syncthreads();

        #pragma unroll
        for (int kk = 0; kk < BK; kk++) {
            float a_frag[TM], b_frag[TN];
            #pragma unroll
            for (int i = 0; i < TM; i++) a_frag[i] = As[kk][ty * TM + i];
            #pragma unroll
            for (int j = 0; j < TN; j++) b_frag[j] = Bs[kk][tx * TN + j];
            #pragma unroll
            for (int i = 0; i < TM; i++)
                #pragma unroll
                for (int j = 0; j < TN; j++)
                    acc[i][j] = fmaf(a_frag[i], b_frag[j], acc[i][j]);
        }
        __syncthreads();
    }

    // Store pre-activations
    #pragma unroll
    for (int i = 0; i < TM; i++) {
        const size_t m = block_m + ty * TM + i;
        #pragma unroll
        for (int j = 0; j < TN; j += 4) {
            float4 v = make_float4(acc[i][j], acc[i][j + 1], acc[i][j + 2], acc[i][j + 3]);
            *(float4*)&g_ifgo[m * NDIM + block_n + tx * TN + j] = v;
        }
    }
}

// ---------------- Epilogue: gates + cell update ----------------
__device__ __forceinline__ float sigf(float v) { return 1.0f / (1.0f + expf(-v)); }

__global__ void lstm_epilogue_kernel(const float* __restrict__ c,
                                     float* __restrict__ out) {
    const int idx = blockIdx.x * blockDim.x + threadIdx.x;  // over B*U/4
    const int m = idx / (UDIM / 4);
    const int u = (idx % (UDIM / 4)) * 4;

    const size_t base = (size_t)m * NDIM + u;
    const float4 iv = *(const float4*)&g_ifgo[base];
    const float4 fv = *(const float4*)&g_ifgo[base + UDIM];
    const float4 gv = *(const float4*)&g_ifgo[base + 2 * UDIM];
    const float4 ov = *(const float4*)&g_ifgo[base + 3 * UDIM];
    const float4 cv = *(const float4*)&c[(size_t)m * UDIM + u];

    float ia[4] = {iv.x, iv.y, iv.z, iv.w};
    float fa[4] = {fv.x, fv.y, fv.z, fv.w};
    float ga[4] = {gv.x, gv.y, gv.z, gv.w};
    float oa[4] = {ov.x, ov.y, ov.z, ov.w};
    float ca[4] = {cv.x, cv.y, cv.z, cv.w};

    float hn[4], cn[4];
    #pragma unroll
    for (int t = 0; t < 4; t++) {
        const float ig = sigf(ia[t]);
        const float fg = sigf(fa[t]);
        const float og = sigf(oa[t]);
        const float gg = tanhf(ga[t]);
        cn[t] = fg * ca[t] + ig * gg;
        hn[t] = og * tanhf(cn[t]);
    }

    const size_t o = (size_t)m * UDIM + u;
    const size_t BU = (size_t)BDIM * UDIM;
    float4 hv = make_float4(hn[0], hn[1], hn[2], hn[3]);
    float4 cnv = make_float4(cn[0], cn[1], cn[2], cn[3]);
    *(float4*)&out[o] = hv;           // h_new
    *(float4*)&out[BU + o] = hv;      // h_new (duplicate per reference tuple)
    *(float4*)&out[2 * BU + o] = cnv; // c_new
}

// ---------------- Launch ----------------
extern "C" void kernel_launch(void* const* d_in, const int* in_sizes, int n_in,
                              void* d_out, int out_size) {
    const float* x = (const float*)d_in[0];
    const float* h = (const float*)d_in[1];
    const float* c = (const float*)d_in[2];
    const float* w = (const float*)d_in[3];
    float* out = (float*)d_out;

    dim3 gemm_grid(NDIM / BN, BDIM / BM);  // (64, 8)
    lstm_gemm_kernel<<<gemm_grid, 256>>>(x, h, w);

    const int total4 = BDIM * UDIM / 4;  // 524288
    lstm_epilogue_kernel<<<total4 / 256, 256>>>(c, out);
}

// round 3
// speedup vs baseline: 3.2379x; 3.2379x over previous
#include <cuda_runtime.h>
#include <cstdint>
#include <math.h>

// Problem dims
#define BDIM 1024
#define UDIM 2048
#define KDIM 4096   // 2*U
#define NDIM 8192   // 4*U

// GEMM tiling
#define MT 128
#define NT 128
#define BK 32
#define AP 36                     // A smem row pitch (floats): banks (4r+c) distinct
#define BP 136                    // B smem row pitch (floats): banks (8k+n) distinct
#define A_STAGE (MT * AP)         // 4608 floats
#define B_STAGE (BK * BP)         // 4352 floats
#define STAGE_FLOATS (A_STAGE + B_STAGE)   // 8960
#define SMEM_BYTES (2 * STAGE_FLOATS * 4)  // 71680 B
#define NCHUNK (KDIM / BK)        // 128

// Scratch for pre-activation gates (32 MB)
__device__ float g_ifgo[(size_t)BDIM * NDIM];

__device__ __forceinline__ uint32_t f2tf32(float f) {
    uint32_t u;
    asm("cvt.rna.tf32.f32 %0, %1;" : "=r"(u) : "f"(f));
    return u;
}

__device__ __forceinline__ void mma_tf32(float d[4], const uint32_t a[4], const uint32_t b[2]) {
    asm volatile(
        "mma.sync.aligned.m16n8k8.row.col.f32.tf32.tf32.f32 "
        "{%0,%1,%2,%3}, {%4,%5,%6,%7}, {%8,%9}, {%0,%1,%2,%3};"
        : "+f"(d[0]), "+f"(d[1]), "+f"(d[2]), "+f"(d[3])
        : "r"(a[0]), "r"(a[1]), "r"(a[2]), "r"(a[3]), "r"(b[0]), "r"(b[1]));
}

// ---------------- GEMM: g_ifgo = concat(x,h) @ w ----------------
__global__ __launch_bounds__(256)
void lstm_gemm_mma(const float* __restrict__ x,
                   const float* __restrict__ h,
                   const float* __restrict__ w) {
    extern __shared__ float smem[];

    const int tid = threadIdx.x;
    const int wid = tid >> 5;
    const int lane = tid & 31;
    const int warp_m = wid >> 2;      // 0..1 -> 64 rows each
    const int warp_n = wid & 3;       // 0..3 -> 32 cols each

    const int m0 = blockIdx.x * MT;   // M fastest -> 8 CTAs share w slab in L2
    const int n0 = blockIdx.y * NT;

    // staging coords
    const int a_row = tid >> 3;       // 0..31 (+32p)
    const int a_c4  = tid & 7;        // float4 col within BK
    const int b_k   = tid >> 5;       // 0..7  (+8p)
    const int b_n4  = tid & 31;       // float4 col within NT

    float acc[4][4][4];
    #pragma unroll
    for (int mt = 0; mt < 4; mt++)
        #pragma unroll
        for (int nt = 0; nt < 4; nt++)
            #pragma unroll
            for (int r = 0; r < 4; r++) acc[mt][nt][r] = 0.f;

    float4 areg[4], breg[4];

    // ---- LDG for chunk c into regs ----
    auto ldg_chunk = [&](int c) {
        const int k0 = c * BK;
        const float* abase = (k0 < UDIM) ? (x + k0) : (h + (k0 - UDIM));
        #pragma unroll
        for (int p = 0; p < 4; p++) {
            const int row = a_row + p * 32;
            areg[p] = *(const float4*)(abase + (size_t)(m0 + row) * UDIM + a_c4 * 4);
        }
        #pragma unroll
        for (int p = 0; p < 4; p++) {
            const int k = b_k + p * 8;
            breg[p] = *(const float4*)(w + (size_t)(k0 + k) * NDIM + n0 + b_n4 * 4);
        }
    };

    // ---- cvt + STS into stage buffer ----
    auto sts_chunk = [&](float* As, float* Bs) {
        #pragma unroll
        for (int p = 0; p < 4; p++) {
            const int row = a_row + p * 32;
            uint4 v = make_uint4(f2tf32(areg[p].x), f2tf32(areg[p].y),
                                 f2tf32(areg[p].z), f2tf32(areg[p].w));
            *(uint4*)(As + row * AP + a_c4 * 4) = v;
        }
        #pragma unroll
        for (int p = 0; p < 4; p++) {
            const int k = b_k + p * 8;
            uint4 v = make_uint4(f2tf32(breg[p].x), f2tf32(breg[p].y),
                                 f2tf32(breg[p].z), f2tf32(breg[p].w));
            *(uint4*)(Bs + k * BP + b_n4 * 4) = v;
        }
    };

    // ---- MMA over one staged chunk ----
    auto compute_chunk = [&](const float* As, const float* Bs) {
        const uint32_t* Au = (const uint32_t*)As;
        const uint32_t* Bu = (const uint32_t*)Bs;
        #pragma unroll
        for (int ks = 0; ks < 4; ks++) {
            uint32_t af[4][4], bf[4][2];
            const int cc = ks * 8 + (lane & 3);
            #pragma unroll
            for (int mt = 0; mt < 4; mt++) {
                const int r0 = warp_m * 64 + mt * 16 + (lane >> 2);
                af[mt][0] = Au[r0 * AP + cc];
                af[mt][1] = Au[(r0 + 8) * AP + cc];
                af[mt][2] = Au[r0 * AP + cc + 4];
                af[mt][3] = Au[(r0 + 8) * AP + cc + 4];
            }
            const int kk = ks * 8 + (lane & 3);
            #pragma unroll
            for (int nt = 0; nt < 4; nt++) {
                const int nn = warp_n * 32 + nt * 8 + (lane >> 2);
                bf[nt][0] = Bu[kk * BP + nn];
                bf[nt][1] = Bu[(kk + 4) * BP + nn];
            }
            #pragma unroll
            for (int mt = 0; mt < 4; mt++)
                #pragma unroll
                for (int nt = 0; nt < 4; nt++)
                    mma_tf32(acc[mt][nt], af[mt], bf[nt]);
        }
    };

    float* stage0 = smem;
    float* stage1 = smem + STAGE_FLOATS;

    ldg_chunk(0);
    sts_chunk(stage0, stage0 + A_STAGE);
    __syncthreads();

    #pragma unroll 1
    for (int c = 0; c < NCHUNK; c++) {
        if (c + 1 < NCHUNK) ldg_chunk(c + 1);
        float* cur = (c & 1) ? stage1 : stage0;
        compute_chunk(cur, cur + A_STAGE);
        if (c + 1 < NCHUNK) {
            float* nxt = (c & 1) ? stage0 : stage1;
            sts_chunk(nxt, nxt + A_STAGE);
            __syncthreads();
        }
    }

    // ---- store accumulators ----
    #pragma unroll
    for (int mt = 0; mt < 4; mt++) {
        const int row = m0 + warp_m * 64 + mt * 16 + (lane >> 2);
        #pragma unroll
        for (int nt = 0; nt < 4; nt++) {
            const int col = n0 + warp_n * 32 + nt * 8 + 2 * (lane & 3);
            float2 v0 = make_float2(acc[mt][nt][0], acc[mt][nt][1]);
            float2 v1 = make_float2(acc[mt][nt][2], acc[mt][nt][3]);
            *(float2*)&g_ifgo[(size_t)row * NDIM + col] = v0;
            *(float2*)&g_ifgo[(size_t)(row + 8) * NDIM + col] = v1;
        }
    }
}

// ---------------- Gating epilogue ----------------
__device__ __forceinline__ float sigf(float v) { return 1.0f / (1.0f + expf(-v)); }

__global__ void lstm_epilogue_kernel(const float* __restrict__ c,
                                     float* __restrict__ out) {
    const int idx = blockIdx.x * blockDim.x + threadIdx.x;
    const int m = idx / (UDIM / 4);
    const int u = (idx % (UDIM / 4)) * 4;

    const size_t base = (size_t)m * NDIM + u;
    const float4 iv = *(const float4*)&g_ifgo[base];
    const float4 fv = *(const float4*)&g_ifgo[base + UDIM];
    const float4 gv = *(const float4*)&g_ifgo[base + 2 * UDIM];
    const float4 ov = *(const float4*)&g_ifgo[base + 3 * UDIM];
    const float4 cv = *(const float4*)&c[(size_t)m * UDIM + u];

    float ia[4] = {iv.x, iv.y, iv.z, iv.w};
    float fa[4] = {fv.x, fv.y, fv.z, fv.w};
    float ga[4] = {gv.x, gv.y, gv.z, gv.w};
    float oa[4] = {ov.x, ov.y, ov.z, ov.w};
    float ca[4] = {cv.x, cv.y, cv.z, cv.w};

    float hn[4], cn[4];
    #pragma unroll
    for (int t = 0; t < 4; t++) {
        const float ig = sigf(ia[t]);
        const float fg = sigf(fa[t]);
        const float og = sigf(oa[t]);
        const float gg = tanhf(ga[t]);
        cn[t] = fg * ca[t] + ig * gg;
        hn[t] = og * tanhf(cn[t]);
    }

    const size_t o = (size_t)m * UDIM + u;
    const size_t BU = (size_t)BDIM * UDIM;
    float4 hv = make_float4(hn[0], hn[1], hn[2], hn[3]);
    float4 cnv = make_float4(cn[0], cn[1], cn[2], cn[3]);
    *(float4*)&out[o] = hv;
    *(float4*)&out[BU + o] = hv;
    *(float4*)&out[2 * BU + o] = cnv;
}

// ---------------- Launch ----------------
extern "C" void kernel_launch(void* const* d_in, const int* in_sizes, int n_in,
                              void* d_out, int out_size) {
    const float* x = (const float*)d_in[0];
    const float* h = (const float*)d_in[1];
    const float* c = (const float*)d_in[2];
    const float* w = (const float*)d_in[3];
    float* out = (float*)d_out;

    cudaFuncSetAttribute(lstm_gemm_mma, cudaFuncAttributeMaxDynamicSharedMemorySize, SMEM_BYTES);

    dim3 grid(BDIM / MT, NDIM / NT);   // (8, 64), M fastest
    lstm_gemm_mma<<<grid, 256, SMEM_BYTES>>>(x, h, w);

    const int total4 = BDIM * UDIM / 4;
    lstm_epilogue_kernel<<<total4 / 256, 256>>>(c, out);
}

// round 4
// speedup vs baseline: 3.4130x; 1.0541x over previous
#include <cuda_runtime.h>
#include <cuda_fp16.h>
#include <cstdint>
#include <math.h>

// Problem dims
#define BDIM 1024
#define UDIM 2048
#define KDIM 4096   // 2*U
#define NDIM 8192   // 4*U

// GEMM tiling
#define MT 128
#define NT 128
#define BK 32
#define PA 40                         // A smem pitch in halves (conflict-free frags)
#define PB 40                         // B smem pitch in halves
#define A_STAGE (MT * PA)             // halves
#define B_STAGE (NT * PB)             // halves (B stored transposed: [n][k])
#define STAGE_HALVES (A_STAGE + B_STAGE)
#define SMEM_BYTES (2 * STAGE_HALVES * 2)   // 40960 B
#define NCHUNK (KDIM / BK)            // 128

// Scratch for pre-activation gates (32 MB)
__device__ float g_ifgo[(size_t)BDIM * NDIM];

__device__ __forceinline__ void mma_f16(float d[4], const uint32_t a[4], const uint32_t b[2]) {
    asm volatile(
        "mma.sync.aligned.m16n8k16.row.col.f32.f16.f16.f32 "
        "{%0,%1,%2,%3}, {%4,%5,%6,%7}, {%8,%9}, {%0,%1,%2,%3};"
        : "+f"(d[0]), "+f"(d[1]), "+f"(d[2]), "+f"(d[3])
        : "r"(a[0]), "r"(a[1]), "r"(a[2]), "r"(a[3]), "r"(b[0]), "r"(b[1]));
}

__device__ __forceinline__ uint32_t pack2(float lo, float hi) {
    half2 h = __floats2half2_rn(lo, hi);
    return *(uint32_t*)&h;
}

// ---------------- GEMM: g_ifgo = concat(x,h) @ w ----------------
__global__ __launch_bounds__(256)
void lstm_gemm_f16(const float* __restrict__ x,
                   const float* __restrict__ h,
                   const float* __restrict__ w) {
    extern __shared__ half smem[];

    const int tid = threadIdx.x;
    const int wid = tid >> 5;
    const int lane = tid & 31;
    const int warp_m = wid >> 2;      // 0..1 -> 64 rows
    const int warp_n = wid & 3;       // 0..3 -> 32 cols

    const int m0 = blockIdx.x * MT;   // M fastest -> 8 CTAs share w slab in L2
    const int n0 = blockIdx.y * NT;

    // A staging coords: row 0..31 (+32p), float4 along k
    const int a_row = tid >> 3;
    const int a_c4  = tid & 7;
    // B staging coords: n 0..127, khalf 0..1 (16 k each, 4 per pass)
    const int b_n    = tid & 127;
    const int b_kh   = tid >> 7;

    float acc[4][4][4];
    #pragma unroll
    for (int mt = 0; mt < 4; mt++)
        #pragma unroll
        for (int nt = 0; nt < 4; nt++)
            #pragma unroll
            for (int r = 0; r < 4; r++) acc[mt][nt][r] = 0.f;

    float4 areg[4];
    float breg[4][4];

    auto ldg_chunk = [&](int c) {
        const int k0 = c * BK;
        const float* abase = (k0 < UDIM) ? (x + k0) : (h + (k0 - UDIM));
        #pragma unroll
        for (int p = 0; p < 4; p++) {
            const int row = a_row + p * 32;
            areg[p] = *(const float4*)(abase + (size_t)(m0 + row) * UDIM + a_c4 * 4);
        }
        // B: 4 coalesced LDG.32 down a w column -> k-consecutive values at fixed n
        #pragma unroll
        for (int p = 0; p < 4; p++) {
            const int k = b_kh * 16 + p * 4;
            const float* wp = w + (size_t)(k0 + k) * NDIM + n0 + b_n;
            breg[p][0] = wp[0];
            breg[p][1] = wp[NDIM];
            breg[p][2] = wp[2 * NDIM];
            breg[p][3] = wp[3 * NDIM];
        }
    };

    auto sts_chunk = [&](half* As, half* Bs) {
        #pragma unroll
        for (int p = 0; p < 4; p++) {
            const int row = a_row + p * 32;
            uint2 v = make_uint2(pack2(areg[p].x, areg[p].y), pack2(areg[p].z, areg[p].w));
            *(uint2*)(As + row * PA + a_c4 * 4) = v;
        }
        #pragma unroll
        for (int p = 0; p < 4; p++) {
            const int k = b_kh * 16 + p * 4;
            uint2 v = make_uint2(pack2(breg[p][0], breg[p][1]), pack2(breg[p][2], breg[p][3]));
            *(uint2*)(Bs + b_n * PB + k) = v;    // transposed: [n][k]
        }
    };

    auto compute_chunk = [&](const half* As, const half* Bs) {
        #pragma unroll
        for (int ks = 0; ks < 2; ks++) {
            const int kb = ks * 16 + 2 * (lane & 3);
            uint32_t af[4][4], bf[4][2];
            #pragma unroll
            for (int mt = 0; mt < 4; mt++) {
                const int r0 = warp_m * 64 + mt * 16 + (lane >> 2);
                const half* ap = As + r0 * PA + kb;
                af[mt][0] = *(const uint32_t*)ap;
                af[mt][1] = *(const uint32_t*)(ap + 8 * PA);
                af[mt][2] = *(const uint32_t*)(ap + 8);
                af[mt][3] = *(const uint32_t*)(ap + 8 * PA + 8);
            }
            #pragma unroll
            for (int nt = 0; nt < 4; nt++) {
                const int nn = warp_n * 32 + nt * 8 + (lane >> 2);
                const half* bp = Bs + nn * PB + kb;
                bf[nt][0] = *(const uint32_t*)bp;
                bf[nt][1] = *(const uint32_t*)(bp + 8);
            }
            #pragma unroll
            for (int mt = 0; mt < 4; mt++)
                #pragma unroll
                for (int nt = 0; nt < 4; nt++)
                    mma_f16(acc[mt][nt], af[mt], bf[nt]);
        }
    };

    half* stage0 = smem;
    half* stage1 = smem + STAGE_HALVES;

    ldg_chunk(0);
    sts_chunk(stage0, stage0 + A_STAGE);
    __syncthreads();

    #pragma unroll 1
    for (int c = 0; c < NCHUNK; c++) {
        if (c + 1 < NCHUNK) ldg_chunk(c + 1);
        half* cur = (c & 1) ? stage1 : stage0;
        compute_chunk(cur, cur + A_STAGE);
        if (c + 1 < NCHUNK) {
            half* nxt = (c & 1) ? stage0 : stage1;
            sts_chunk(nxt, nxt + A_STAGE);
            __syncthreads();
        }
    }

    // ---- store accumulators ----
    #pragma unroll
    for (int mt = 0; mt < 4; mt++) {
        const int row = m0 + warp_m * 64 + mt * 16 + (lane >> 2);
        #pragma unroll
        for (int nt = 0; nt < 4; nt++) {
            const int col = n0 + warp_n * 32 + nt * 8 + 2 * (lane & 3);
            float2 v0 = make_float2(acc[mt][nt][0], acc[mt][nt][1]);
            float2 v1 = make_float2(acc[mt][nt][2], acc[mt][nt][3]);
            *(float2*)&g_ifgo[(size_t)row * NDIM + col] = v0;
            *(float2*)&g_ifgo[(size_t)(row + 8) * NDIM + col] = v1;
        }
    }
}

// ---------------- Gating epilogue ----------------
__device__ __forceinline__ float sigf(float v) { return 1.0f / (1.0f + expf(-v)); }

__global__ void lstm_epilogue_kernel(const float* __restrict__ c,
                                     float* __restrict__ out) {
    const int idx = blockIdx.x * blockDim.x + threadIdx.x;
    const int m = idx / (UDIM / 4);
    const int u = (idx % (UDIM / 4)) * 4;

    const size_t base = (size_t)m * NDIM + u;
    const float4 iv = *(const float4*)&g_ifgo[base];
    const float4 fv = *(const float4*)&g_ifgo[base + UDIM];
    const float4 gv = *(const float4*)&g_ifgo[base + 2 * UDIM];
    const float4 ov = *(const float4*)&g_ifgo[base + 3 * UDIM];
    const float4 cv = *(const float4*)&c[(size_t)m * UDIM + u];

    float ia[4] = {iv.x, iv.y, iv.z, iv.w};
    float fa[4] = {fv.x, fv.y, fv.z, fv.w};
    float ga[4] = {gv.x, gv.y, gv.z, gv.w};
    float oa[4] = {ov.x, ov.y, ov.z, ov.w};
    float ca[4] = {cv.x, cv.y, cv.z, cv.w};

    float hn[4], cn[4];
    #pragma unroll
    for (int t = 0; t < 4; t++) {
        const float ig = sigf(ia[t]);
        const float fg = sigf(fa[t]);
        const float og = sigf(oa[t]);
        const float gg = tanhf(ga[t]);
        cn[t] = fg * ca[t] + ig * gg;
        hn[t] = og * tanhf(cn[t]);
    }

    const size_t o = (size_t)m * UDIM + u;
    const size_t BU = (size_t)BDIM * UDIM;
    float4 hv = make_float4(hn[0], hn[1], hn[2], hn[3]);
    float4 cnv = make_float4(cn[0], cn[1], cn[2], cn[3]);
    *(float4*)&out[o] = hv;
    *(float4*)&out[BU + o] = hv;
    *(float4*)&out[2 * BU + o] = cnv;
}

// ---------------- Launch ----------------
extern "C" void kernel_launch(void* const* d_in, const int* in_sizes, int n_in,
                              void* d_out, int out_size) {
    const float* x = (const float*)d_in[0];
    const float* h = (const float*)d_in[1];
    const float* c = (const float*)d_in[2];
    const float* w = (const float*)d_in[3];
    float* out = (float*)d_out;

    cudaFuncSetAttribute(lstm_gemm_f16, cudaFuncAttributeMaxDynamicSharedMemorySize, SMEM_BYTES);

    dim3 grid(BDIM / MT, NDIM / NT);   // (8, 64), M fastest
    lstm_gemm_f16<<<grid, 256, SMEM_BYTES>>>(x, h, w);

    const int total4 = BDIM * UDIM / 4;
    lstm_epilogue_kernel<<<total4 / 256, 256>>>(c, out);
}